// round 16
// baseline (speedup 1.0000x reference)
#include <cuda_runtime.h>
#include <cuda_fp16.h>
#include <cstdint>

// Problem constants (B=1)
#define SLEN 1024
#define DMODEL 512
#define HDIM 64
#define NTOK 8192
#define NHASH 8
#define JCHZ 32    // z-pass j-chunks  -> 2048 CTAs
#define JCHO 32    // out-pass j-chunks -> 2048 CTAs
#define PADB 144   // padded smem row stride (bytes) -> conflict-free ldmatrix
#define EX2A 0.18033688f    // 0.125 * log2(e)
#define EX2B -11.54156032f  // -8 * log2(e)
#define EX2MAX 15.8696454f  // 11 * log2(e)

// ---------------------------------------------------------------------------
// Scratch (device globals; no allocation allowed)
__device__ float    g_qkf[NTOK * HDIM];
__device__ __half   g_qh [NTOK * HDIM];
__device__ __half   g_ql [NTOK * HDIM];
__device__ __half   g_vth[HDIM * NTOK];   // V^T: [d][n], single fp16
__device__ float    g_attn[NTOK * HDIM];
__device__ float    g_z  [NTOK * NHASH];  // raw Z sums (inverted in out-pass)
__device__ unsigned g_code[NTOK];
__device__ __half   g_eh [(size_t)NTOK * NTOK];  // exp(S/8 - 8), fp16, 128MB

// ---------------------------------------------------------------------------
__device__ __forceinline__ uint32_t smem_u32(const void* p) {
    uint32_t a;
    asm("{ .reg .u64 t; cvta.to.shared.u64 t, %1; cvt.u32.u64 %0, t; }" : "=r"(a) : "l"(p));
    return a;
}
__device__ __forceinline__ void ldmat_x4(uint32_t* r, uint32_t addr) {
    asm volatile("ldmatrix.sync.aligned.m8n8.x4.shared.b16 {%0,%1,%2,%3}, [%4];"
                 : "=r"(r[0]), "=r"(r[1]), "=r"(r[2]), "=r"(r[3]) : "r"(addr));
}
__device__ __forceinline__ void mma_f16(float* c, const uint32_t* a, const uint32_t* b) {
    asm volatile("mma.sync.aligned.m16n8k16.row.col.f32.f16.f16.f32 "
                 "{%0,%1,%2,%3},{%4,%5,%6,%7},{%8,%9},{%0,%1,%2,%3};"
                 : "+f"(c[0]), "+f"(c[1]), "+f"(c[2]), "+f"(c[3])
                 : "r"(a[0]), "r"(a[1]), "r"(a[2]), "r"(a[3]), "r"(b[0]), "r"(b[1]));
}
__device__ __forceinline__ void cp_async16(uint32_t dst, const void* src) {
    asm volatile("cp.async.cg.shared.global [%0], [%1], 16;" :: "r"(dst), "l"(src));
}
#define CP_COMMIT() asm volatile("cp.async.commit_group;" ::: "memory")
#define CP_WAIT0()  asm volatile("cp.async.wait_group 0;" ::: "memory")
#define CP_WAIT1()  asm volatile("cp.async.wait_group 1;" ::: "memory")

__device__ __forceinline__ float ex2f(float x) {
    float y;
    asm("ex2.approx.f32 %0, %1;" : "=f"(y) : "f"(x));
    return y;
}
__device__ __forceinline__ unsigned nzmask(unsigned x) {
    unsigned nz = x | ((x & 0x77777777u) + 0x77777777u);
    return ~nz & 0x88888888u;
}
__device__ __forceinline__ void zadd(float* z, unsigned zm, float e) {
    if (zm & 0x00000008u) z[0] += e;
    if (zm & 0x00000080u) z[1] += e;
    if (zm & 0x00000800u) z[2] += e;
    if (zm & 0x00008000u) z[3] += e;
    if (zm & 0x00080000u) z[4] += e;
    if (zm & 0x00800000u) z[5] += e;
    if (zm & 0x08000000u) z[6] += e;
    if (zm & 0x80000000u) z[7] += e;
}
__device__ __forceinline__ float zsum(unsigned zm, const float* iz) {
    float s = 0.f;
    s += (zm & 0x00000008u) ? iz[0] : 0.f;
    s += (zm & 0x00000080u) ? iz[1] : 0.f;
    s += (zm & 0x00000800u) ? iz[2] : 0.f;
    s += (zm & 0x00008000u) ? iz[3] : 0.f;
    s += (zm & 0x00080000u) ? iz[4] : 0.f;
    s += (zm & 0x00800000u) ? iz[5] : 0.f;
    s += (zm & 0x08000000u) ? iz[6] : 0.f;
    s += (zm & 0x80000000u) ? iz[7] : 0.f;
    return s;
}

// ---------------------------------------------------------------------------
// Fused zeroing: g_z, g_attn, and y (y needed zeroed for split-K final)
__global__ void k_zero(float* __restrict__ y) {
    int i = blockIdx.x * blockDim.x + threadIdx.x;
    if (i < NTOK * NHASH) g_z[i] = 0.f;
    if (i < NTOK * HDIM)  g_attn[i] = 0.f;
    if (i < SLEN * DMODEL) y[i] = 0.f;
}

// ---------------------------------------------------------------------------
// Projection GEMM, both projections in one launch (blockIdx.z selects).
// z==0 -> qk (fp32 + fp16 splits), z==1 -> V^T (fp16)
__global__ void k_proj(const float* __restrict__ x,
                       const float* __restrict__ w_qk, const float* __restrict__ b_qk,
                       const float* __restrict__ w_v,  const float* __restrict__ b_v) {
    __shared__ float sX[64][17];
    __shared__ float sW[16][65];
    int which = blockIdx.z;
    const float* w = which ? w_v : w_qk;
    const float* b = which ? b_v : b_qk;
    int tid = threadIdx.x;
    int tx = tid & 15, ty = tid >> 4;
    int s0 = blockIdx.y * 64;
    int m0 = blockIdx.x * 64;
    float acc[4][4];
#pragma unroll
    for (int q = 0; q < 4; q++)
#pragma unroll
        for (int p = 0; p < 4; p++) acc[q][p] = 0.f;

    for (int k0 = 0; k0 < DMODEL; k0 += 16) {
        for (int t = tid; t < 1024; t += 256) {
            sX[t >> 4][t & 15] = x[(s0 + (t >> 4)) * DMODEL + k0 + (t & 15)];
            sW[t >> 6][t & 63] = w[(k0 + (t >> 6)) * DMODEL + m0 + (t & 63)];
        }
        __syncthreads();
#pragma unroll
        for (int kk = 0; kk < 16; kk++) {
            float a[4], bb[4];
#pragma unroll
            for (int q = 0; q < 4; q++) a[q] = sX[ty * 4 + q][kk];
#pragma unroll
            for (int p = 0; p < 4; p++) bb[p] = sW[kk][tx * 4 + p];
#pragma unroll
            for (int q = 0; q < 4; q++)
#pragma unroll
                for (int p = 0; p < 4; p++) acc[q][p] += a[q] * bb[p];
        }
        __syncthreads();
    }
#pragma unroll
    for (int q = 0; q < 4; q++) {
        int s = s0 + ty * 4 + q;
#pragma unroll
        for (int p = 0; p < 4; p++) {
            int m = m0 + tx * 4 + p;
            float val = acc[q][p] + b[m];
            int n = (m >> 6) * SLEN + s;
            int d = m & 63;
            __half h = __float2half_rn(val);
            if (which == 0) {
                __half l = __float2half_rn(val - __half2float(h));
                g_qkf[n * HDIM + d] = val;
                g_qh[n * HDIM + d] = h;
                g_ql[n * HDIM + d] = l;
            } else {
                g_vth[d * NTOK + n] = h;
            }
        }
    }
}

// ---------------------------------------------------------------------------
// LSH hashing: 128 CTAs x 64 threads (one thread per token)
__global__ void __launch_bounds__(64) k_hash(const float* __restrict__ rot) {
    __shared__ float s_rot[8 * 64 * 8];
    int b = blockIdx.x;
    int h = b >> 4;
    int tid = threadIdx.x;
    int n = h * 1024 + (b & 15) * 64 + tid;

    for (int t = tid; t < 4096; t += 64) {
        int r = t >> 9, dc = t & 511;
        s_rot[t] = rot[((size_t)(r * 8 + h) << 9) + dc];
    }
    __syncthreads();

    float q[64];
    const float4* qp = reinterpret_cast<const float4*>(g_qkf + n * HDIM);
#pragma unroll
    for (int i = 0; i < 16; i++) {
        float4 f = qp[i];
        q[4 * i] = f.x; q[4 * i + 1] = f.y; q[4 * i + 2] = f.z; q[4 * i + 3] = f.w;
    }

    unsigned code = 0u;
    for (int r = 0; r < NHASH; r++) {
        const float* rp = s_rot + r * 512;
        float v[8];
#pragma unroll
        for (int c = 0; c < 8; c++) v[c] = 0.f;
#pragma unroll
        for (int d = 0; d < 64; d++) {
            float qd = q[d];
#pragma unroll
            for (int c = 0; c < 8; c++) v[c] += qd * rp[d * 8 + c];
        }
        float best = v[0];
        int bi = 0;
#pragma unroll
        for (int t = 1; t < 16; t++) {
            float x = (t < 8) ? v[t] : -v[t - 8];
            if (x > best) { best = x; bi = t; }
        }
        code |= ((unsigned)bi) << (4 * r);
    }
    g_code[n] = code;
}

// ---------------------------------------------------------------------------
// Pass A: S via fp16 2-term mma; e = fp16(exp(S/8 - 8)) cached (dense stores).
#define ZA_CI      0
#define ZA_CJ(b)   (512 + (b) * 256)
#define ZA_QIH     1024
#define ZA_QJH(b)  (ZA_QIH + 128 * PADB + (b) * 2 * 64 * PADB)
#define ZA_QJL(b)  (ZA_QJH(b) + 64 * PADB)
#define ZA_SMEM    (ZA_QIH + 128 * PADB + 4 * 64 * PADB)

__device__ __forceinline__ void z_issue(char* sm, int buf, int j0, int tid) {
    const char* qh = reinterpret_cast<const char*>(g_qh);
    const char* ql = reinterpret_cast<const char*>(g_ql);
    for (int t = tid; t < 1024; t += 256) {
        int tensor = t >> 9;
        int idx = t & 511;
        int r = idx >> 3, c = idx & 7;
        uint32_t dst = smem_u32(sm + (tensor ? ZA_QJL(buf) : ZA_QJH(buf)) + r * PADB + c * 16);
        cp_async16(dst, (tensor ? ql : qh) + (size_t)(j0 + r) * 128 + c * 16);
    }
    if (tid < 16) {
        uint32_t dst = smem_u32(sm + ZA_CJ(buf) + tid * 16);
        cp_async16(dst, reinterpret_cast<const char*>(g_code) + (size_t)j0 * 4 + tid * 16);
    }
    CP_COMMIT();
}

__global__ void __launch_bounds__(256) k_zpass() {
    extern __shared__ char sm[];
    uint32_t sb = smem_u32(sm);
    int tid = threadIdx.x, wid = tid >> 5, lane = tid & 31;
    int i0 = blockIdx.x * 128;

    const uint32_t* qh32 = reinterpret_cast<const uint32_t*>(g_qh);
    for (int t = tid; t < 4096; t += 256) {
        int r = t >> 5, c = t & 31;
        *reinterpret_cast<uint32_t*>(sm + ZA_QIH + r * PADB + c * 4) = qh32[(i0 + r) * 32 + c];
    }
    if (tid < 128) reinterpret_cast<unsigned*>(sm + ZA_CI)[tid] = g_code[i0 + tid];

    int jt0 = blockIdx.y * (128 / JCHZ), jtn = jt0 + 128 / JCHZ;
    z_issue(sm, 0, jt0 * 64, tid);
    __syncthreads();

    int m0 = wid * 16;
    int row0 = m0 + (lane >> 2), row1 = row0 + 8;
    unsigned ci0 = reinterpret_cast<unsigned*>(sm + ZA_CI)[row0];
    unsigned ci1 = reinterpret_cast<unsigned*>(sm + ZA_CI)[row1];

    uint32_t ah[4][4];
    uint32_t arow = m0 + (lane & 7) + ((lane >> 3) & 1) * 8;
#pragma unroll
    for (int kt = 0; kt < 4; kt++) {
        uint32_t acolb = (kt * 16 + (lane >> 4) * 8) * 2;
        ldmat_x4(ah[kt], sb + ZA_QIH + arow * PADB + acolb);
    }

    float z0[8], z1[8];
#pragma unroll
    for (int r = 0; r < 8; r++) { z0[r] = 0.f; z1[r] = 0.f; }

    for (int jt = jt0; jt < jtn; jt++) {
        int buf = (jt - jt0) & 1;
        int j0 = jt * 64;
        if (jt + 1 < jtn) { z_issue(sm, buf ^ 1, (jt + 1) * 64, tid); CP_WAIT1(); }
        else CP_WAIT0();
        __syncthreads();

#pragma unroll
        for (int nt = 0; nt < 8; nt++) {
            int n0 = nt * 8;
            float C[4] = {0.f, 0.f, 0.f, 0.f};
            uint32_t brow = n0 + (lane & 7);
#pragma unroll
            for (int half = 0; half < 2; half++) {
                uint32_t bcolb = (half * 32 + (lane >> 3) * 8) * 2;
                uint32_t bh[4], bl[4];
                ldmat_x4(bh, sb + ZA_QJH(buf) + brow * PADB + bcolb);
                ldmat_x4(bl, sb + ZA_QJL(buf) + brow * PADB + bcolb);
#pragma unroll
                for (int s = 0; s < 2; s++) {
                    int kt = half * 2 + s;
                    mma_f16(C, ah[kt], &bh[s * 2]);
                    mma_f16(C, ah[kt], &bl[s * 2]);
                }
            }
            int col0 = n0 + 2 * (lane & 3);
            float ef0 = ex2f(fminf(fmaf(C[0], EX2A, EX2B), EX2MAX));
            float ef1 = ex2f(fminf(fmaf(C[1], EX2A, EX2B), EX2MAX));
            float ef2 = ex2f(fminf(fmaf(C[2], EX2A, EX2B), EX2MAX));
            float ef3 = ex2f(fminf(fmaf(C[3], EX2A, EX2B), EX2MAX));
            __half2 e01 = __floats2half2_rn(ef0, ef1);
            __half2 e23 = __floats2half2_rn(ef2, ef3);
            *reinterpret_cast<__half2*>(&g_eh[((size_t)(i0 + row0) << 13) + j0 + col0]) = e01;
            *reinterpret_cast<__half2*>(&g_eh[((size_t)(i0 + row1) << 13) + j0 + col0]) = e23;

            unsigned cj0 = reinterpret_cast<unsigned*>(sm + ZA_CJ(buf))[col0];
            unsigned cj1 = reinterpret_cast<unsigned*>(sm + ZA_CJ(buf))[col0 + 1];
            unsigned zm;
            zm = nzmask(ci0 ^ cj0); if (zm) zadd(z0, zm, ef0);
            zm = nzmask(ci0 ^ cj1); if (zm) zadd(z0, zm, ef1);
            zm = nzmask(ci1 ^ cj0); if (zm) zadd(z1, zm, ef2);
            zm = nzmask(ci1 ^ cj1); if (zm) zadd(z1, zm, ef3);
        }
        __syncthreads();
    }
#pragma unroll
    for (int r = 0; r < 8; r++) {
        z0[r] += __shfl_xor_sync(0xffffffffu, z0[r], 1);
        z0[r] += __shfl_xor_sync(0xffffffffu, z0[r], 2);
        z1[r] += __shfl_xor_sync(0xffffffffu, z1[r], 1);
        z1[r] += __shfl_xor_sync(0xffffffffu, z1[r], 2);
    }
    if ((lane & 3) == 0) {
#pragma unroll
        for (int r = 0; r < 8; r++) {
            atomicAdd(&g_z[(i0 + row0) * NHASH + r], z0[r]);
            atomicAdd(&g_z[(i0 + row1) * NHASH + r], z1[r]);
        }
    }
}

// ---------------------------------------------------------------------------
// Pass B: iz computed locally (0.125/Z); P = e * zsum via HMUL2; PV single-term V.
// e loads software-pipelined by one nt.
#define OB_CI      0
#define OB_CJ(b)   (512 + (b) * 256)
#define OB_VTH(b)  (1024 + (b) * 64 * PADB)
#define OB_SMEM    (1024 + 2 * 64 * PADB)

__device__ __forceinline__ void o_issue(char* sm, int buf, int j0, int tid) {
    const char* vh = reinterpret_cast<const char*>(g_vth);
    for (int t = tid; t < 512; t += 256) {
        int r = t >> 3, c = t & 7;
        uint32_t dst = smem_u32(sm + OB_VTH(buf) + r * PADB + c * 16);
        cp_async16(dst, vh + ((size_t)r * NTOK + j0) * 2 + c * 16);
    }
    if (tid < 16) {
        uint32_t dst = smem_u32(sm + OB_CJ(buf) + tid * 16);
        cp_async16(dst, reinterpret_cast<const char*>(g_code) + (size_t)j0 * 4 + tid * 16);
    }
    CP_COMMIT();
}

__global__ void __launch_bounds__(256, 3) k_outpass() {
    extern __shared__ char sm[];
    uint32_t sb = smem_u32(sm);
    int tid = threadIdx.x, wid = tid >> 5, lane = tid & 31;
    int i0 = blockIdx.x * 128;

    if (tid < 128) reinterpret_cast<unsigned*>(sm + OB_CI)[tid] = g_code[i0 + tid];

    int jt0 = blockIdx.y * (128 / JCHO), jtn = jt0 + 128 / JCHO;
    o_issue(sm, 0, jt0 * 64, tid);
    __syncthreads();

    int m0 = wid * 16;
    int row0 = m0 + (lane >> 2), row1 = row0 + 8;
    unsigned ci0 = reinterpret_cast<unsigned*>(sm + OB_CI)[row0];
    unsigned ci1 = reinterpret_cast<unsigned*>(sm + OB_CI)[row1];
    float iz0[8], iz1[8];
#pragma unroll
    for (int r = 0; r < 8; r++) {
        iz0[r] = 0.125f / g_z[(i0 + row0) * NHASH + r];
        iz1[r] = 0.125f / g_z[(i0 + row1) * NHASH + r];
    }

    float O[8][4];
#pragma unroll
    for (int dt = 0; dt < 8; dt++)
#pragma unroll
        for (int q = 0; q < 4; q++) O[dt][q] = 0.f;

    const size_t erow0 = (size_t)(i0 + row0) << 13;
    const size_t erow1 = (size_t)(i0 + row1) << 13;
    int lc = 2 * (lane & 3);

    for (int jt = jt0; jt < jtn; jt++) {
        int buf = (jt - jt0) & 1;
        int j0 = jt * 64;
        if (jt + 1 < jtn) { o_issue(sm, buf ^ 1, (jt + 1) * 64, tid); CP_WAIT1(); }
        else CP_WAIT0();
        __syncthreads();

        // --- build P in registers (A-fragment layout), pipelined e loads ---
        uint32_t pl[8], ph[8];
        __half2 pe01 = *reinterpret_cast<const __half2*>(&g_eh[erow0 + j0 + lc]);
        __half2 pe23 = *reinterpret_cast<const __half2*>(&g_eh[erow1 + j0 + lc]);
#pragma unroll
        for (int nt = 0; nt < 8; nt++) {
            __half2 e01 = pe01, e23 = pe23;
            if (nt < 7) {
                int coln = (nt + 1) * 8 + lc;
                pe01 = *reinterpret_cast<const __half2*>(&g_eh[erow0 + j0 + coln]);
                pe23 = *reinterpret_cast<const __half2*>(&g_eh[erow1 + j0 + coln]);
            }
            int col0 = nt * 8 + lc;
            unsigned cj0 = reinterpret_cast<unsigned*>(sm + OB_CJ(buf))[col0];
            unsigned cj1 = reinterpret_cast<unsigned*>(sm + OB_CJ(buf))[col0 + 1];
            float zs00 = zsum(nzmask(ci0 ^ cj0), iz0);
            float zs01 = zsum(nzmask(ci0 ^ cj1), iz0);
            float zs10 = zsum(nzmask(ci1 ^ cj0), iz1);
            float zs11 = zsum(nzmask(ci1 ^ cj1), iz1);
            __half2 hp0 = __hmul2(e01, __floats2half2_rn(zs00, zs01));
            __half2 hp1 = __hmul2(e23, __floats2half2_rn(zs10, zs11));
            pl[nt] = *reinterpret_cast<uint32_t*>(&hp0);
            ph[nt] = *reinterpret_cast<uint32_t*>(&hp1);
        }

        // --- OUT += P @ V^T (single-term V) ---
#pragma unroll
        for (int dt = 0; dt < 8; dt++) {
            int d0 = dt * 8;
            uint32_t brow = d0 + (lane & 7);
#pragma unroll
            for (int half = 0; half < 2; half++) {
                uint32_t bcolb = (half * 32 + (lane >> 3) * 8) * 2;
                uint32_t bh[4];
                ldmat_x4(bh, sb + OB_VTH(buf) + brow * PADB + bcolb);
#pragma unroll
                for (int s = 0; s < 2; s++) {
                    int kt = half * 2 + s;
                    uint32_t A[4] = { pl[2 * kt], ph[2 * kt], pl[2 * kt + 1], ph[2 * kt + 1] };
                    mma_f16(O[dt], A, &bh[s * 2]);
                }
            }
        }
        __syncthreads();
    }
#pragma unroll
    for (int dt = 0; dt < 8; dt++) {
        int c0 = dt * 8 + lc;
        atomicAdd(&g_attn[(i0 + row0) * HDIM + c0],     O[dt][0]);
        atomicAdd(&g_attn[(i0 + row0) * HDIM + c0 + 1], O[dt][1]);
        atomicAdd(&g_attn[(i0 + row1) * HDIM + c0],     O[dt][2]);
        atomicAdd(&g_attn[(i0 + row1) * HDIM + c0 + 1], O[dt][3]);
    }
}

// ---------------------------------------------------------------------------
// Final output GEMM, split-K x4 over blockIdx.z (atomicAdd into zeroed y).
__global__ void k_final(const float* __restrict__ w_o, const float* __restrict__ b_o,
                        float* __restrict__ y) {
    __shared__ float sA[64][17];
    __shared__ float sW[16][65];
    int tid = threadIdx.x;
    int tx = tid & 15, ty = tid >> 4;
    int s0 = blockIdx.y * 64;
    int m0 = blockIdx.x * 64;
    int kz = blockIdx.z;           // 0..3, each covers 128 of K=512
    float acc[4][4];
#pragma unroll
    for (int q = 0; q < 4; q++)
#pragma unroll
        for (int p = 0; p < 4; p++) acc[q][p] = 0.f;

    for (int k0 = kz * 128; k0 < kz * 128 + 128; k0 += 16) {
        for (int t = tid; t < 1024; t += 256) {
            int r = t >> 4, c = t & 15;
            int k = k0 + c;
            sA[r][c] = g_attn[((k >> 6) * SLEN + s0 + r) * HDIM + (k & 63)];
            sW[t >> 6][t & 63] = w_o[(k0 + (t >> 6)) * DMODEL + m0 + (t & 63)];
        }
        __syncthreads();
#pragma unroll
        for (int kk = 0; kk < 16; kk++) {
            float a[4], bb[4];
#pragma unroll
            for (int q = 0; q < 4; q++) a[q] = sA[ty * 4 + q][kk];
#pragma unroll
            for (int p = 0; p < 4; p++) bb[p] = sW[kk][tx * 4 + p];
#pragma unroll
            for (int q = 0; q < 4; q++)
#pragma unroll
                for (int p = 0; p < 4; p++) acc[q][p] += a[q] * bb[p];
        }
        __syncthreads();
    }
#pragma unroll
    for (int q = 0; q < 4; q++) {
        int s = s0 + ty * 4 + q;
#pragma unroll
        for (int p = 0; p < 4; p++) {
            int m = m0 + tx * 4 + p;
            float v = acc[q][p] + (kz == 0 ? b_o[m] : 0.f);
            atomicAdd(&y[s * DMODEL + m], v);
        }
    }
}

// ---------------------------------------------------------------------------
extern "C" void kernel_launch(void* const* d_in, const int* in_sizes, int n_in,
                              void* d_out, int out_size) {
    const float* x    = (const float*)d_in[0];
    const float* w_qk = (const float*)d_in[1];
    const float* b_qk = (const float*)d_in[2];
    const float* w_v  = (const float*)d_in[3];
    const float* b_v  = (const float*)d_in[4];
    const float* w_o  = (const float*)d_in[5];
    const float* b_o  = (const float*)d_in[6];
    const float* rot  = (const float*)d_in[7];
    float* y = (float*)d_out;

    cudaFuncSetAttribute(k_zpass, cudaFuncAttributeMaxDynamicSharedMemorySize, ZA_SMEM);
    cudaFuncSetAttribute(k_outpass, cudaFuncAttributeMaxDynamicSharedMemorySize, OB_SMEM);

    k_zero<<<2048, 256>>>(y);
    k_proj<<<dim3(8, 16, 2), 256>>>(x, w_qk, b_qk, w_v, b_v);
    k_hash<<<128, 64>>>(rot);
    k_zpass<<<dim3(64, JCHZ), 256, ZA_SMEM>>>();
    k_outpass<<<dim3(64, JCHO), 256, OB_SMEM>>>();
    k_final<<<dim3(8, 16, 4), 256>>>(w_o, b_o, y);
}

// round 17
// speedup vs baseline: 1.0279x; 1.0279x over previous
#include <cuda_runtime.h>
#include <cuda_fp16.h>
#include <cstdint>

// Problem constants (B=1)
#define SLEN 1024
#define DMODEL 512
#define HDIM 64
#define NTOK 8192
#define NHASH 8
#define JCHZ 32    // z-pass j-chunks  -> 2048 CTAs
#define JCHO 32    // out-pass j-chunks -> 2048 CTAs
#define PADB 144   // padded smem row stride (bytes) -> conflict-free ldmatrix
#define EX2A 0.18033688f    // 0.125 * log2(e)
#define EX2B -11.54156032f  // -8 * log2(e)
#define EX2MAX 15.8696454f  // 11 * log2(e)

// ---------------------------------------------------------------------------
// Scratch (device globals; no allocation allowed)
__device__ float    g_qkf[NTOK * HDIM];
__device__ __half   g_qh [NTOK * HDIM];
__device__ __half   g_ql [NTOK * HDIM];
__device__ __half   g_vth[HDIM * NTOK];   // V^T: [d][n], single fp16
__device__ float    g_attn[NTOK * HDIM];
__device__ float    g_z  [NTOK * NHASH];  // raw Z sums (inverted in out-pass)
__device__ unsigned g_code[NTOK];
__device__ __half   g_eh [(size_t)NTOK * NTOK];  // exp(S/8 - 8), fp16, 128MB

// ---------------------------------------------------------------------------
__device__ __forceinline__ uint32_t smem_u32(const void* p) {
    uint32_t a;
    asm("{ .reg .u64 t; cvta.to.shared.u64 t, %1; cvt.u32.u64 %0, t; }" : "=r"(a) : "l"(p));
    return a;
}
__device__ __forceinline__ void ldmat_x4(uint32_t* r, uint32_t addr) {
    asm volatile("ldmatrix.sync.aligned.m8n8.x4.shared.b16 {%0,%1,%2,%3}, [%4];"
                 : "=r"(r[0]), "=r"(r[1]), "=r"(r[2]), "=r"(r[3]) : "r"(addr));
}
__device__ __forceinline__ void mma_f16(float* c, const uint32_t* a, const uint32_t* b) {
    asm volatile("mma.sync.aligned.m16n8k16.row.col.f32.f16.f16.f32 "
                 "{%0,%1,%2,%3},{%4,%5,%6,%7},{%8,%9},{%0,%1,%2,%3};"
                 : "+f"(c[0]), "+f"(c[1]), "+f"(c[2]), "+f"(c[3])
                 : "r"(a[0]), "r"(a[1]), "r"(a[2]), "r"(a[3]), "r"(b[0]), "r"(b[1]));
}
__device__ __forceinline__ void cp_async16(uint32_t dst, const void* src) {
    asm volatile("cp.async.cg.shared.global [%0], [%1], 16;" :: "r"(dst), "l"(src));
}
#define CP_COMMIT() asm volatile("cp.async.commit_group;" ::: "memory")
#define CP_WAIT0()  asm volatile("cp.async.wait_group 0;" ::: "memory")
#define CP_WAIT1()  asm volatile("cp.async.wait_group 1;" ::: "memory")

__device__ __forceinline__ float ex2f(float x) {
    float y;
    asm("ex2.approx.f32 %0, %1;" : "=f"(y) : "f"(x));
    return y;
}
__device__ __forceinline__ unsigned nzmask(unsigned x) {
    unsigned nz = x | ((x & 0x77777777u) + 0x77777777u);
    return ~nz & 0x88888888u;
}
__device__ __forceinline__ void zadd(float* z, unsigned zm, float e) {
    if (zm & 0x00000008u) z[0] += e;
    if (zm & 0x00000080u) z[1] += e;
    if (zm & 0x00000800u) z[2] += e;
    if (zm & 0x00008000u) z[3] += e;
    if (zm & 0x00080000u) z[4] += e;
    if (zm & 0x00800000u) z[5] += e;
    if (zm & 0x08000000u) z[6] += e;
    if (zm & 0x80000000u) z[7] += e;
}
__device__ __forceinline__ float zsum(unsigned zm, const float* iz) {
    float s = 0.f;
    s += (zm & 0x00000008u) ? iz[0] : 0.f;
    s += (zm & 0x00000080u) ? iz[1] : 0.f;
    s += (zm & 0x00000800u) ? iz[2] : 0.f;
    s += (zm & 0x00008000u) ? iz[3] : 0.f;
    s += (zm & 0x00080000u) ? iz[4] : 0.f;
    s += (zm & 0x00800000u) ? iz[5] : 0.f;
    s += (zm & 0x08000000u) ? iz[6] : 0.f;
    s += (zm & 0x80000000u) ? iz[7] : 0.f;
    return s;
}

// ---------------------------------------------------------------------------
// Fused zeroing: g_z, g_attn, and y (y needed zeroed for split-K final)
__global__ void k_zero(float* __restrict__ y) {
    int i = blockIdx.x * blockDim.x + threadIdx.x;
    if (i < NTOK * NHASH) g_z[i] = 0.f;
    if (i < NTOK * HDIM)  g_attn[i] = 0.f;
    if (i < SLEN * DMODEL) y[i] = 0.f;
}

// ---------------------------------------------------------------------------
// Projection GEMM, both projections in one launch (blockIdx.z selects).
// z==0 -> qk (fp32 + fp16 splits), z==1 -> V^T (fp16)
__global__ void k_proj(const float* __restrict__ x,
                       const float* __restrict__ w_qk, const float* __restrict__ b_qk,
                       const float* __restrict__ w_v,  const float* __restrict__ b_v) {
    __shared__ float sX[64][17];
    __shared__ float sW[16][65];
    int which = blockIdx.z;
    const float* w = which ? w_v : w_qk;
    const float* b = which ? b_v : b_qk;
    int tid = threadIdx.x;
    int tx = tid & 15, ty = tid >> 4;
    int s0 = blockIdx.y * 64;
    int m0 = blockIdx.x * 64;
    float acc[4][4];
#pragma unroll
    for (int q = 0; q < 4; q++)
#pragma unroll
        for (int p = 0; p < 4; p++) acc[q][p] = 0.f;

    for (int k0 = 0; k0 < DMODEL; k0 += 16) {
        for (int t = tid; t < 1024; t += 256) {
            sX[t >> 4][t & 15] = x[(s0 + (t >> 4)) * DMODEL + k0 + (t & 15)];
            sW[t >> 6][t & 63] = w[(k0 + (t >> 6)) * DMODEL + m0 + (t & 63)];
        }
        __syncthreads();
#pragma unroll
        for (int kk = 0; kk < 16; kk++) {
            float a[4], bb[4];
#pragma unroll
            for (int q = 0; q < 4; q++) a[q] = sX[ty * 4 + q][kk];
#pragma unroll
            for (int p = 0; p < 4; p++) bb[p] = sW[kk][tx * 4 + p];
#pragma unroll
            for (int q = 0; q < 4; q++)
#pragma unroll
                for (int p = 0; p < 4; p++) acc[q][p] += a[q] * bb[p];
        }
        __syncthreads();
    }
#pragma unroll
    for (int q = 0; q < 4; q++) {
        int s = s0 + ty * 4 + q;
#pragma unroll
        for (int p = 0; p < 4; p++) {
            int m = m0 + tx * 4 + p;
            float val = acc[q][p] + b[m];
            int n = (m >> 6) * SLEN + s;
            int d = m & 63;
            __half h = __float2half_rn(val);
            if (which == 0) {
                __half l = __float2half_rn(val - __half2float(h));
                g_qkf[n * HDIM + d] = val;
                g_qh[n * HDIM + d] = h;
                g_ql[n * HDIM + d] = l;
            } else {
                g_vth[d * NTOK + n] = h;
            }
        }
    }
}

// ---------------------------------------------------------------------------
// LSH hashing: 128 CTAs x 64 threads (one thread per token)
__global__ void __launch_bounds__(64) k_hash(const float* __restrict__ rot) {
    __shared__ float s_rot[8 * 64 * 8];
    int b = blockIdx.x;
    int h = b >> 4;
    int tid = threadIdx.x;
    int n = h * 1024 + (b & 15) * 64 + tid;

    for (int t = tid; t < 4096; t += 64) {
        int r = t >> 9, dc = t & 511;
        s_rot[t] = rot[((size_t)(r * 8 + h) << 9) + dc];
    }
    __syncthreads();

    float q[64];
    const float4* qp = reinterpret_cast<const float4*>(g_qkf + n * HDIM);
#pragma unroll
    for (int i = 0; i < 16; i++) {
        float4 f = qp[i];
        q[4 * i] = f.x; q[4 * i + 1] = f.y; q[4 * i + 2] = f.z; q[4 * i + 3] = f.w;
    }

    unsigned code = 0u;
    for (int r = 0; r < NHASH; r++) {
        const float* rp = s_rot + r * 512;
        float v[8];
#pragma unroll
        for (int c = 0; c < 8; c++) v[c] = 0.f;
#pragma unroll
        for (int d = 0; d < 64; d++) {
            float qd = q[d];
#pragma unroll
            for (int c = 0; c < 8; c++) v[c] += qd * rp[d * 8 + c];
        }
        float best = v[0];
        int bi = 0;
#pragma unroll
        for (int t = 1; t < 16; t++) {
            float x = (t < 8) ? v[t] : -v[t - 8];
            if (x > best) { best = x; bi = t; }
        }
        code |= ((unsigned)bi) << (4 * r);
    }
    g_code[n] = code;
}

// ---------------------------------------------------------------------------
// Pass A: S via fp16 2-term mma; e = fp16(exp(S/8 - 8)) cached (dense stores).
#define ZA_CI      0
#define ZA_CJ(b)   (512 + (b) * 256)
#define ZA_QIH     1024
#define ZA_QJH(b)  (ZA_QIH + 128 * PADB + (b) * 2 * 64 * PADB)
#define ZA_QJL(b)  (ZA_QJH(b) + 64 * PADB)
#define ZA_SMEM    (ZA_QIH + 128 * PADB + 4 * 64 * PADB)

__device__ __forceinline__ void z_issue(char* sm, int buf, int j0, int tid) {
    const char* qh = reinterpret_cast<const char*>(g_qh);
    const char* ql = reinterpret_cast<const char*>(g_ql);
    for (int t = tid; t < 1024; t += 256) {
        int tensor = t >> 9;
        int idx = t & 511;
        int r = idx >> 3, c = idx & 7;
        uint32_t dst = smem_u32(sm + (tensor ? ZA_QJL(buf) : ZA_QJH(buf)) + r * PADB + c * 16);
        cp_async16(dst, (tensor ? ql : qh) + (size_t)(j0 + r) * 128 + c * 16);
    }
    if (tid < 16) {
        uint32_t dst = smem_u32(sm + ZA_CJ(buf) + tid * 16);
        cp_async16(dst, reinterpret_cast<const char*>(g_code) + (size_t)j0 * 4 + tid * 16);
    }
    CP_COMMIT();
}

__global__ void __launch_bounds__(256) k_zpass() {
    extern __shared__ char sm[];
    uint32_t sb = smem_u32(sm);
    int tid = threadIdx.x, wid = tid >> 5, lane = tid & 31;
    int i0 = blockIdx.x * 128;

    const uint32_t* qh32 = reinterpret_cast<const uint32_t*>(g_qh);
    for (int t = tid; t < 4096; t += 256) {
        int r = t >> 5, c = t & 31;
        *reinterpret_cast<uint32_t*>(sm + ZA_QIH + r * PADB + c * 4) = qh32[(i0 + r) * 32 + c];
    }
    if (tid < 128) reinterpret_cast<unsigned*>(sm + ZA_CI)[tid] = g_code[i0 + tid];

    int jt0 = blockIdx.y * (128 / JCHZ), jtn = jt0 + 128 / JCHZ;
    z_issue(sm, 0, jt0 * 64, tid);
    __syncthreads();

    int m0 = wid * 16;
    int row0 = m0 + (lane >> 2), row1 = row0 + 8;
    unsigned ci0 = reinterpret_cast<unsigned*>(sm + ZA_CI)[row0];
    unsigned ci1 = reinterpret_cast<unsigned*>(sm + ZA_CI)[row1];

    uint32_t ah[4][4];
    uint32_t arow = m0 + (lane & 7) + ((lane >> 3) & 1) * 8;
#pragma unroll
    for (int kt = 0; kt < 4; kt++) {
        uint32_t acolb = (kt * 16 + (lane >> 4) * 8) * 2;
        ldmat_x4(ah[kt], sb + ZA_QIH + arow * PADB + acolb);
    }

    float z0[8], z1[8];
#pragma unroll
    for (int r = 0; r < 8; r++) { z0[r] = 0.f; z1[r] = 0.f; }

    for (int jt = jt0; jt < jtn; jt++) {
        int buf = (jt - jt0) & 1;
        int j0 = jt * 64;
        if (jt + 1 < jtn) { z_issue(sm, buf ^ 1, (jt + 1) * 64, tid); CP_WAIT1(); }
        else CP_WAIT0();
        __syncthreads();

#pragma unroll
        for (int nt = 0; nt < 8; nt++) {
            int n0 = nt * 8;
            float C[4] = {0.f, 0.f, 0.f, 0.f};
            uint32_t brow = n0 + (lane & 7);
#pragma unroll
            for (int half = 0; half < 2; half++) {
                uint32_t bcolb = (half * 32 + (lane >> 3) * 8) * 2;
                uint32_t bh[4], bl[4];
                ldmat_x4(bh, sb + ZA_QJH(buf) + brow * PADB + bcolb);
                ldmat_x4(bl, sb + ZA_QJL(buf) + brow * PADB + bcolb);
#pragma unroll
                for (int s = 0; s < 2; s++) {
                    int kt = half * 2 + s;
                    mma_f16(C, ah[kt], &bh[s * 2]);
                    mma_f16(C, ah[kt], &bl[s * 2]);
                }
            }
            int col0 = n0 + 2 * (lane & 3);
            __half h0 = __float2half_rn(ex2f(fminf(fmaf(C[0], EX2A, EX2B), EX2MAX)));
            __half h1 = __float2half_rn(ex2f(fminf(fmaf(C[1], EX2A, EX2B), EX2MAX)));
            __half h2 = __float2half_rn(ex2f(fminf(fmaf(C[2], EX2A, EX2B), EX2MAX)));
            __half h3 = __float2half_rn(ex2f(fminf(fmaf(C[3], EX2A, EX2B), EX2MAX)));
            __half2 e01; e01.x = h0; e01.y = h1;
            __half2 e23; e23.x = h2; e23.y = h3;
            *reinterpret_cast<__half2*>(&g_eh[((size_t)(i0 + row0) << 13) + j0 + col0]) = e01;
            *reinterpret_cast<__half2*>(&g_eh[((size_t)(i0 + row1) << 13) + j0 + col0]) = e23;

            unsigned cj0 = reinterpret_cast<unsigned*>(sm + ZA_CJ(buf))[col0];
            unsigned cj1 = reinterpret_cast<unsigned*>(sm + ZA_CJ(buf))[col0 + 1];
            unsigned zm;
            zm = nzmask(ci0 ^ cj0); if (zm) zadd(z0, zm, __half2float(h0));
            zm = nzmask(ci0 ^ cj1); if (zm) zadd(z0, zm, __half2float(h1));
            zm = nzmask(ci1 ^ cj0); if (zm) zadd(z1, zm, __half2float(h2));
            zm = nzmask(ci1 ^ cj1); if (zm) zadd(z1, zm, __half2float(h3));
        }
        __syncthreads();
    }
#pragma unroll
    for (int r = 0; r < 8; r++) {
        z0[r] += __shfl_xor_sync(0xffffffffu, z0[r], 1);
        z0[r] += __shfl_xor_sync(0xffffffffu, z0[r], 2);
        z1[r] += __shfl_xor_sync(0xffffffffu, z1[r], 1);
        z1[r] += __shfl_xor_sync(0xffffffffu, z1[r], 2);
    }
    if ((lane & 3) == 0) {
#pragma unroll
        for (int r = 0; r < 8; r++) {
            atomicAdd(&g_z[(i0 + row0) * NHASH + r], z0[r]);
            atomicAdd(&g_z[(i0 + row1) * NHASH + r], z1[r]);
        }
    }
}

// ---------------------------------------------------------------------------
// Pass B: iz computed locally (0.125/Z); P = e * zsum via HMUL2; PV single-term V.
// e loads software-pipelined by one nt.
#define OB_CI      0
#define OB_CJ(b)   (512 + (b) * 256)
#define OB_VTH(b)  (1024 + (b) * 64 * PADB)
#define OB_SMEM    (1024 + 2 * 64 * PADB)

__device__ __forceinline__ void o_issue(char* sm, int buf, int j0, int tid) {
    const char* vh = reinterpret_cast<const char*>(g_vth);
    for (int t = tid; t < 512; t += 256) {
        int r = t >> 3, c = t & 7;
        uint32_t dst = smem_u32(sm + OB_VTH(buf) + r * PADB + c * 16);
        cp_async16(dst, vh + ((size_t)r * NTOK + j0) * 2 + c * 16);
    }
    if (tid < 16) {
        uint32_t dst = smem_u32(sm + OB_CJ(buf) + tid * 16);
        cp_async16(dst, reinterpret_cast<const char*>(g_code) + (size_t)j0 * 4 + tid * 16);
    }
    CP_COMMIT();
}

__global__ void __launch_bounds__(256, 3) k_outpass() {
    extern __shared__ char sm[];
    uint32_t sb = smem_u32(sm);
    int tid = threadIdx.x, wid = tid >> 5, lane = tid & 31;
    int i0 = blockIdx.x * 128;

    if (tid < 128) reinterpret_cast<unsigned*>(sm + OB_CI)[tid] = g_code[i0 + tid];

    int jt0 = blockIdx.y * (128 / JCHO), jtn = jt0 + 128 / JCHO;
    o_issue(sm, 0, jt0 * 64, tid);
    __syncthreads();

    int m0 = wid * 16;
    int row0 = m0 + (lane >> 2), row1 = row0 + 8;
    unsigned ci0 = reinterpret_cast<unsigned*>(sm + OB_CI)[row0];
    unsigned ci1 = reinterpret_cast<unsigned*>(sm + OB_CI)[row1];
    float iz0[8], iz1[8];
#pragma unroll
    for (int r = 0; r < 8; r++) {
        iz0[r] = 0.125f / g_z[(i0 + row0) * NHASH + r];
        iz1[r] = 0.125f / g_z[(i0 + row1) * NHASH + r];
    }

    float O[8][4];
#pragma unroll
    for (int dt = 0; dt < 8; dt++)
#pragma unroll
        for (int q = 0; q < 4; q++) O[dt][q] = 0.f;

    const size_t erow0 = (size_t)(i0 + row0) << 13;
    const size_t erow1 = (size_t)(i0 + row1) << 13;
    int lc = 2 * (lane & 3);

    for (int jt = jt0; jt < jtn; jt++) {
        int buf = (jt - jt0) & 1;
        int j0 = jt * 64;
        if (jt + 1 < jtn) { o_issue(sm, buf ^ 1, (jt + 1) * 64, tid); CP_WAIT1(); }
        else CP_WAIT0();
        __syncthreads();

        // --- build P in registers (A-fragment layout), pipelined e loads ---
        uint32_t pl[8], ph[8];
        __half2 pe01 = *reinterpret_cast<const __half2*>(&g_eh[erow0 + j0 + lc]);
        __half2 pe23 = *reinterpret_cast<const __half2*>(&g_eh[erow1 + j0 + lc]);
#pragma unroll
        for (int nt = 0; nt < 8; nt++) {
            __half2 e01 = pe01, e23 = pe23;
            if (nt < 7) {
                int coln = (nt + 1) * 8 + lc;
                pe01 = *reinterpret_cast<const __half2*>(&g_eh[erow0 + j0 + coln]);
                pe23 = *reinterpret_cast<const __half2*>(&g_eh[erow1 + j0 + coln]);
            }
            int col0 = nt * 8 + lc;
            unsigned cj0 = reinterpret_cast<unsigned*>(sm + OB_CJ(buf))[col0];
            unsigned cj1 = reinterpret_cast<unsigned*>(sm + OB_CJ(buf))[col0 + 1];
            float zs00 = zsum(nzmask(ci0 ^ cj0), iz0);
            float zs01 = zsum(nzmask(ci0 ^ cj1), iz0);
            float zs10 = zsum(nzmask(ci1 ^ cj0), iz1);
            float zs11 = zsum(nzmask(ci1 ^ cj1), iz1);
            __half2 hp0 = __hmul2(e01, __floats2half2_rn(zs00, zs01));
            __half2 hp1 = __hmul2(e23, __floats2half2_rn(zs10, zs11));
            pl[nt] = *reinterpret_cast<uint32_t*>(&hp0);
            ph[nt] = *reinterpret_cast<uint32_t*>(&hp1);
        }

        // --- OUT += P @ V^T (single-term V) ---
#pragma unroll
        for (int dt = 0; dt < 8; dt++) {
            int d0 = dt * 8;
            uint32_t brow = d0 + (lane & 7);
#pragma unroll
            for (int half = 0; half < 2; half++) {
                uint32_t bcolb = (half * 32 + (lane >> 3) * 8) * 2;
                uint32_t bh[4];
                ldmat_x4(bh, sb + OB_VTH(buf) + brow * PADB + bcolb);
#pragma unroll
                for (int s = 0; s < 2; s++) {
                    int kt = half * 2 + s;
                    uint32_t A[4] = { pl[2 * kt], ph[2 * kt], pl[2 * kt + 1], ph[2 * kt + 1] };
                    mma_f16(O[dt], A, &bh[s * 2]);
                }
            }
        }
        __syncthreads();
    }
#pragma unroll
    for (int dt = 0; dt < 8; dt++) {
        int c0 = dt * 8 + lc;
        atomicAdd(&g_attn[(i0 + row0) * HDIM + c0],     O[dt][0]);
        atomicAdd(&g_attn[(i0 + row0) * HDIM + c0 + 1], O[dt][1]);
        atomicAdd(&g_attn[(i0 + row1) * HDIM + c0],     O[dt][2]);
        atomicAdd(&g_attn[(i0 + row1) * HDIM + c0 + 1], O[dt][3]);
    }
}

// ---------------------------------------------------------------------------
// Final output GEMM, split-K x4 over blockIdx.z (atomicAdd into zeroed y).
__global__ void k_final(const float* __restrict__ w_o, const float* __restrict__ b_o,
                        float* __restrict__ y) {
    __shared__ float sA[64][17];
    __shared__ float sW[16][65];
    int tid = threadIdx.x;
    int tx = tid & 15, ty = tid >> 4;
    int s0 = blockIdx.y * 64;
    int m0 = blockIdx.x * 64;
    int kz = blockIdx.z;           // 0..3, each covers 128 of K=512
    float acc[4][4];
#pragma unroll
    for (int q = 0; q < 4; q++)
#pragma unroll
        for (int p = 0; p < 4; p++) acc[q][p] = 0.f;

    for (int k0 = kz * 128; k0 < kz * 128 + 128; k0 += 16) {
        for (int t = tid; t < 1024; t += 256) {
            int r = t >> 4, c = t & 15;
            int k = k0 + c;
            sA[r][c] = g_attn[((k >> 6) * SLEN + s0 + r) * HDIM + (k & 63)];
            sW[t >> 6][t & 63] = w_o[(k0 + (t >> 6)) * DMODEL + m0 + (t & 63)];
        }
        __syncthreads();
#pragma unroll
        for (int kk = 0; kk < 16; kk++) {
            float a[4], bb[4];
#pragma unroll
            for (int q = 0; q < 4; q++) a[q] = sA[ty * 4 + q][kk];
#pragma unroll
            for (int p = 0; p < 4; p++) bb[p] = sW[kk][tx * 4 + p];
#pragma unroll
            for (int q = 0; q < 4; q++)
#pragma unroll
                for (int p = 0; p < 4; p++) acc[q][p] += a[q] * bb[p];
        }
        __syncthreads();
    }
#pragma unroll
    for (int q = 0; q < 4; q++) {
        int s = s0 + ty * 4 + q;
#pragma unroll
        for (int p = 0; p < 4; p++) {
            int m = m0 + tx * 4 + p;
            float v = acc[q][p] + (kz == 0 ? b_o[m] : 0.f);
            atomicAdd(&y[s * DMODEL + m], v);
        }
    }
}

// ---------------------------------------------------------------------------
extern "C" void kernel_launch(void* const* d_in, const int* in_sizes, int n_in,
                              void* d_out, int out_size) {
    const float* x    = (const float*)d_in[0];
    const float* w_qk = (const float*)d_in[1];
    const float* b_qk = (const float*)d_in[2];
    const float* w_v  = (const float*)d_in[3];
    const float* b_v  = (const float*)d_in[4];
    const float* w_o  = (const float*)d_in[5];
    const float* b_o  = (const float*)d_in[6];
    const float* rot  = (const float*)d_in[7];
    float* y = (float*)d_out;

    cudaFuncSetAttribute(k_zpass, cudaFuncAttributeMaxDynamicSharedMemorySize, ZA_SMEM);
    cudaFuncSetAttribute(k_outpass, cudaFuncAttributeMaxDynamicSharedMemorySize, OB_SMEM);

    k_zero<<<2048, 256>>>(y);
    k_proj<<<dim3(8, 16, 2), 256>>>(x, w_qk, b_qk, w_v, b_v);
    k_hash<<<128, 64>>>(rot);
    k_zpass<<<dim3(64, JCHZ), 256, ZA_SMEM>>>();
    k_outpass<<<dim3(64, JCHO), 256, OB_SMEM>>>();
    k_final<<<dim3(8, 16, 4), 256>>>(w_o, b_o, y);
}